// round 2
// baseline (speedup 1.0000x reference)
#include <cuda_runtime.h>
#include <cuda_bf16.h>

// CrossNetwork (DCN-v1): x_{l+1} = input * (x_l . w_l) + x_l + b_l, L=6 steps.
//
// Closed form: x_l = alpha_l * input + y_l with
//   y_l = sum_{j<l} b_j                      (row-independent [D] vector)
//   q_l = y_l . w_l                          (row-independent scalar)
//   p_l = input_row . w_l                    (per-row scalar, all on x_0)
//   alpha_{l+1} = alpha_l * (1 + p_l) + q_l,  alpha_0 = 1
//   output_row  = alpha_L * input_row + y_L
//
// => one HBM read of input, one HBM write of output (128 MB total),
//    6 simultaneous dot products in a single streaming pass.

#define D 1024
#define L 6
#define NTHREADS 256
#define ROWS_PER_BLOCK 16   // 8 warps * 2 rows/warp
#define D4 (D / 4)          // 256 float4 per row

__global__ __launch_bounds__(NTHREADS, 2)
void crossnet_kernel(const float* __restrict__ input,
                     const float* __restrict__ Wg,
                     const float* __restrict__ bg,
                     float* __restrict__ out,
                     int B)
{
    __shared__ float4 w_s[L * D4];   // 24 KB: full W
    __shared__ float4 y_s[D4];       // 4 KB: y_L = sum_l b_l
    __shared__ float  q_s[L];        // 6 scalars

    const int tid  = threadIdx.x;
    const int lane = tid & 31;
    const int warp = tid >> 5;

    if (tid < L) q_s[tid] = 0.0f;

    // ---- preamble: load W into smem (coalesced float4) ----
    const float4* W4 = reinterpret_cast<const float4*>(Wg);
    const float4* B4 = reinterpret_cast<const float4*>(bg);
#pragma unroll
    for (int i = 0; i < L; i++)
        w_s[i * D4 + tid] = W4[i * D4 + tid];
    __syncthreads();

    // ---- compute y_L and q_l (redundantly per block; trivial cost) ----
    {
        // thread tid owns float4 column group tid (d = 4*tid .. 4*tid+3)
        float4 y = make_float4(0.f, 0.f, 0.f, 0.f);
        float ql[L];
#pragma unroll
        for (int l = 0; l < L; l++) {
            float4 w  = w_s[l * D4 + tid];
            float4 bb = B4[l * D4 + tid];        // L2-hot global read (24 KB)
            ql[l] = y.x * w.x + y.y * w.y + y.z * w.z + y.w * w.w;
            y.x += bb.x; y.y += bb.y; y.z += bb.z; y.w += bb.w;
        }
        y_s[tid] = y;
#pragma unroll
        for (int l = 0; l < L; l++) {
            float v = ql[l];
#pragma unroll
            for (int o = 16; o > 0; o >>= 1)
                v += __shfl_xor_sync(0xffffffffu, v, o);
            if (lane == 0) atomicAdd(&q_s[l], v);
        }
    }
    __syncthreads();

    // ---- main: each warp handles 2 rows, input held in registers ----
    const int row0 = blockIdx.x * ROWS_PER_BLOCK + warp * 2;
    const bool r0ok = (row0 < B);
    const bool r1ok = (row0 + 1 < B);
    if (!r0ok) return;

    const float4* in0p = reinterpret_cast<const float4*>(input) + (size_t)row0 * D4;
    const float4* in1p = in0p + D4;

    float4 in0[8], in1[8];
#pragma unroll
    for (int k = 0; k < 8; k++) {
        in0[k] = in0p[lane + 32 * k];
        in1[k] = r1ok ? in1p[lane + 32 * k] : make_float4(0.f, 0.f, 0.f, 0.f);
    }

    float acc0[L], acc1[L];
#pragma unroll
    for (int l = 0; l < L; l++) { acc0[l] = 0.f; acc1[l] = 0.f; }

    // 6 dots per row; W read from smem once per warp, reused for both rows
#pragma unroll
    for (int k = 0; k < 8; k++) {
#pragma unroll
        for (int l = 0; l < L; l++) {
            float4 w = w_s[l * D4 + lane + 32 * k];
            acc0[l] = fmaf(in0[k].x, w.x, acc0[l]);
            acc0[l] = fmaf(in0[k].y, w.y, acc0[l]);
            acc0[l] = fmaf(in0[k].z, w.z, acc0[l]);
            acc0[l] = fmaf(in0[k].w, w.w, acc0[l]);
            acc1[l] = fmaf(in1[k].x, w.x, acc1[l]);
            acc1[l] = fmaf(in1[k].y, w.y, acc1[l]);
            acc1[l] = fmaf(in1[k].z, w.z, acc1[l]);
            acc1[l] = fmaf(in1[k].w, w.w, acc1[l]);
        }
    }

    // butterfly warp reductions -> every lane holds full p_l
#pragma unroll
    for (int l = 0; l < L; l++) {
#pragma unroll
        for (int o = 16; o > 0; o >>= 1) {
            acc0[l] += __shfl_xor_sync(0xffffffffu, acc0[l], o);
            acc1[l] += __shfl_xor_sync(0xffffffffu, acc1[l], o);
        }
    }

    // scalar recurrence: alpha = alpha*(1+p) + q
    float a0 = 1.0f, a1 = 1.0f;
#pragma unroll
    for (int l = 0; l < L; l++) {
        float q = q_s[l];
        a0 = fmaf(a0, acc0[l], a0) + q;
        a1 = fmaf(a1, acc1[l], a1) + q;
    }

    // ---- output: out = alpha * input + y_L ----
    float4* o0 = reinterpret_cast<float4*>(out) + (size_t)row0 * D4;
    float4* o1 = o0 + D4;
#pragma unroll
    for (int k = 0; k < 8; k++) {
        float4 y = y_s[lane + 32 * k];
        float4 r0, r1;
        r0.x = fmaf(a0, in0[k].x, y.x);
        r0.y = fmaf(a0, in0[k].y, y.y);
        r0.z = fmaf(a0, in0[k].z, y.z);
        r0.w = fmaf(a0, in0[k].w, y.w);
        r1.x = fmaf(a1, in1[k].x, y.x);
        r1.y = fmaf(a1, in1[k].y, y.y);
        r1.z = fmaf(a1, in1[k].z, y.z);
        r1.w = fmaf(a1, in1[k].w, y.w);
        o0[lane + 32 * k] = r0;
        if (r1ok) o1[lane + 32 * k] = r1;
    }
}

extern "C" void kernel_launch(void* const* d_in, const int* in_sizes, int n_in,
                              void* d_out, int out_size)
{
    const float* input = (const float*)d_in[0];
    const float* W     = (const float*)d_in[1];
    const float* b     = (const float*)d_in[2];
    float* out         = (float*)d_out;

    const int B    = in_sizes[0] / D;                         // 16384
    const int grid = (B + ROWS_PER_BLOCK - 1) / ROWS_PER_BLOCK; // 1024

    crossnet_kernel<<<grid, NTHREADS>>>(input, W, b, out, B);
}